// round 5
// baseline (speedup 1.0000x reference)
#include <cuda_runtime.h>
#include <cfloat>

#define B   32
#define C   512
#define H   56
#define W   56
#define HW  (H * W)          // 3136
#define HW4 (HW / 4)         // 784
#define W4  (W / 4)          // 14
#define KD  768
#define NTOT ((size_t)B * C * HW)

// pooling block geometry: 16 hw4-columns x 16 channel-chunks
#define PTX 16
#define PTY 16
#define PCC (C / PTY)        // 32 channels per chunk
#define PBLK_PER_B (HW4 / PTX)   // 49

// fused conv+mul tiling
#define CROWS 4              // output rows per stripe
#define CTH   (CROWS + 6)    // tile rows incl halo
#define CTW   64             // padded tile width
#define NPOS  (CROWS * W)    // 224 scalar positions per stripe
#define NPOS4 (NPOS / 4)     // 56 float4 positions
#define CSPL  4              // channel chunks
#define CCH   (C / CSPL)     // 128 channels per chunk

// Scratch (alloc-free rule: __device__ globals)
__device__ float g_pooled[B * 2 * HW];
__device__ float g_bias[B];

// ---------------------------------------------------------------------------
// Kernel 1: fused channel max+mean pooling (R3-proven).
// ---------------------------------------------------------------------------
__global__ void pool_kernel(const float4* __restrict__ x4) {
    int tx = threadIdx.x & (PTX - 1);
    int ty = threadIdx.x >> 4;
    int b   = blockIdx.y;
    int hw4 = blockIdx.x * PTX + tx;

    const float4* p = x4 + (size_t)b * C * HW4
                         + (size_t)ty * PCC * HW4 + hw4;
    float4 v0 = __ldg(p);
    float4 mx = v0;
    float4 sm = v0;
#pragma unroll
    for (int c = 1; c < PCC; ++c) {
        float4 v = __ldg(p + (size_t)c * HW4);
        mx.x = fmaxf(mx.x, v.x); mx.y = fmaxf(mx.y, v.y);
        mx.z = fmaxf(mx.z, v.z); mx.w = fmaxf(mx.w, v.w);
        sm.x += v.x; sm.y += v.y; sm.z += v.z; sm.w += v.w;
    }

    __shared__ float4 smax[PTY][PTX];
    __shared__ float4 ssum[PTY][PTX];
    smax[ty][tx] = mx;
    ssum[ty][tx] = sm;
    __syncthreads();

#pragma unroll
    for (int s = PTY / 2; s > 0; s >>= 1) {
        if (ty < s) {
            float4 m = smax[ty + s][tx];
            float4 q = ssum[ty + s][tx];
            mx.x = fmaxf(mx.x, m.x); mx.y = fmaxf(mx.y, m.y);
            mx.z = fmaxf(mx.z, m.z); mx.w = fmaxf(mx.w, m.w);
            sm.x += q.x; sm.y += q.y; sm.z += q.z; sm.w += q.w;
            smax[ty][tx] = mx;
            ssum[ty][tx] = sm;
        }
        __syncthreads();
    }

    if (ty == 0) {
        const float inv = 1.0f / C;
        sm.x *= inv; sm.y *= inv; sm.z *= inv; sm.w *= inv;
        float4* pool4 = reinterpret_cast<float4*>(g_pooled);
        pool4[(b * 2 * HW) / 4 + hw4]      = mx;
        pool4[(b * 2 * HW + HW) / 4 + hw4] = sm;
    }
}

// ---------------------------------------------------------------------------
// Kernel 2: keyword bias. One block per batch.
// ---------------------------------------------------------------------------
__global__ void bias_kernel(const float* __restrict__ keyword,
                            const float* __restrict__ proj_w,
                            const float* __restrict__ proj_b) {
    int b = blockIdx.x;
    int tid = threadIdx.x;
    float s = 0.0f;
    for (int k = tid; k < KD; k += blockDim.x)
        s += keyword[b * KD + k] * proj_w[k];
#pragma unroll
    for (int off = 16; off > 0; off >>= 1)
        s += __shfl_down_sync(0xFFFFFFFFu, s, off);
    __shared__ float smem[8];
    if ((tid & 31) == 0) smem[tid >> 5] = s;
    __syncthreads();
    if (tid == 0) {
        float t = 0.0f;
        int nw = blockDim.x >> 5;
        for (int i = 0; i < nw; ++i) t += smem[i];
        g_bias[b] = t + proj_b[0];
    }
}

// ---------------------------------------------------------------------------
// Kernel 3: FUSED conv(7x7)+sigmoid+gate-multiply.
// grid = (H/CROWS=14, CSPL=4, B=32) = 1792 blocks, 256 threads.
// Phase A: compute scale for this 4-row stripe into smem (redundant per
//          channel chunk — trivial FLOPs).
// Phase B: stream 128 channels x 56 float4: out = x * scale.
// ---------------------------------------------------------------------------
__global__ void fused_mul_kernel(const float4* __restrict__ x4,
                                 float4* __restrict__ out4,
                                 const float* __restrict__ conv_w,
                                 const float* __restrict__ conv_b) {
    __shared__ float tile[2][CTH][CTW];   // 5 KB
    __shared__ float wts[98];
    __shared__ float sbias;
    __shared__ float4 sscale4[NPOS4];     // 56 float4 = 224 scales

    int stripe = blockIdx.x;
    int cchunk = blockIdx.y;
    int b      = blockIdx.z;
    int r0     = stripe * CROWS;
    int tid    = threadIdx.x;

    if (tid < 98) wts[tid] = conv_w[tid];
    if (tid == 0) sbias = conv_b[0] + g_bias[b];

    // tile load (2ch x 10 x 64, zero-padded halo)
    const float* pb = g_pooled + b * 2 * HW;
    for (int i = tid; i < 2 * CTH * CTW; i += 256) {
        int ci = i / (CTH * CTW);
        int rr = (i / CTW) % CTH;
        int cc = i % CTW;
        int hh = r0 + rr - 3;
        int ww = cc - 3;
        float v = 0.0f;
        if ((unsigned)hh < (unsigned)H && (unsigned)ww < (unsigned)W)
            v = pb[ci * HW + hh * W + ww];
        tile[ci][rr][cc] = v;
    }
    __syncthreads();

    // conv + sigmoid for 224 positions
    if (tid < NPOS) {
        int r = tid / W;
        int w = tid - r * W;
        float acc = sbias;
#pragma unroll
        for (int ci = 0; ci < 2; ++ci) {
#pragma unroll
            for (int kh = 0; kh < 7; ++kh) {
#pragma unroll
                for (int kw = 0; kw < 7; ++kw) {
                    acc += tile[ci][r + kh][w + kw] * wts[ci * 49 + kh * 7 + kw];
                }
            }
        }
        reinterpret_cast<float*>(sscale4)[tid] = 1.0f / (1.0f + __expf(-acc));
    }
    __syncthreads();

    // stream: 128 channels x 56 float4 per block
    const size_t base = (size_t)(b * C + cchunk * CCH) * HW4 + stripe * NPOS4;
#pragma unroll 4
    for (int i = tid; i < CCH * NPOS4; i += 256) {
        int cl = i / NPOS4;          // channel within chunk
        int p  = i - cl * NPOS4;     // float4 position in stripe
        size_t g = base + (size_t)cl * HW4 + p;
        float4 s = sscale4[p];
        float4 v = __ldcs(x4 + g);
        v.x *= s.x; v.y *= s.y; v.z *= s.z; v.w *= s.w;
        __stcs(out4 + g, v);
    }
}

// ---------------------------------------------------------------------------
extern "C" void kernel_launch(void* const* d_in, const int* in_sizes, int n_in,
                              void* d_out, int out_size) {
    const float* x       = (const float*)d_in[0];
    const float* keyword = (const float*)d_in[1];
    const float* conv_w  = (const float*)d_in[2];
    const float* conv_b  = (const float*)d_in[3];
    const float* proj_w  = (const float*)d_in[4];
    const float* proj_b  = (const float*)d_in[5];
    float* out = (float*)d_out;

    bias_kernel<<<B, 256>>>(keyword, proj_w, proj_b);
    {
        dim3 grid(PBLK_PER_B, B);        // 49 x 32
        pool_kernel<<<grid, PTX * PTY>>>((const float4*)x);
    }
    {
        dim3 grid(H / CROWS, CSPL, B);   // 14 x 4 x 32 = 1792
        fused_mul_kernel<<<grid, 256>>>((const float4*)x, (float4*)out,
                                        conv_w, conv_b);
    }
}

// round 6
// speedup vs baseline: 1.1127x; 1.1127x over previous
#include <cuda_runtime.h>
#include <cfloat>

#define B   32
#define C   512
#define H   56
#define W   56
#define HW  (H * W)          // 3136
#define HW4 (HW / 4)         // 784
#define KD  768
#define NTOT ((size_t)B * C * HW)

// pooling block geometry: 16 hw4-columns x 16 channel-chunks
#define PTX 16
#define PTY 16
#define PCC (C / PTY)        // 32 channels per chunk
#define PBLK_PER_B (HW4 / PTX)   // 49

// conv tiling
#define CROWS 4
#define CTH   (CROWS + 6)
#define CTW   64

// Scratch (alloc-free rule: __device__ globals)
__device__ float g_pooled[B * 2 * HW];
__device__ float g_scale[B * HW];

// ---------------------------------------------------------------------------
// Kernel 1: fused channel max+mean pooling (R3-proven).
// ---------------------------------------------------------------------------
__global__ void pool_kernel(const float4* __restrict__ x4) {
    int tx = threadIdx.x & (PTX - 1);
    int ty = threadIdx.x >> 4;
    int b   = blockIdx.y;
    int hw4 = blockIdx.x * PTX + tx;

    const float4* p = x4 + (size_t)b * C * HW4
                         + (size_t)ty * PCC * HW4 + hw4;
    float4 v0 = __ldg(p);
    float4 mx = v0;
    float4 sm = v0;
#pragma unroll
    for (int c = 1; c < PCC; ++c) {
        float4 v = __ldg(p + (size_t)c * HW4);
        mx.x = fmaxf(mx.x, v.x); mx.y = fmaxf(mx.y, v.y);
        mx.z = fmaxf(mx.z, v.z); mx.w = fmaxf(mx.w, v.w);
        sm.x += v.x; sm.y += v.y; sm.z += v.z; sm.w += v.w;
    }

    __shared__ float4 smax[PTY][PTX];
    __shared__ float4 ssum[PTY][PTX];
    smax[ty][tx] = mx;
    ssum[ty][tx] = sm;
    __syncthreads();

#pragma unroll
    for (int s = PTY / 2; s > 0; s >>= 1) {
        if (ty < s) {
            float4 m = smax[ty + s][tx];
            float4 q = ssum[ty + s][tx];
            mx.x = fmaxf(mx.x, m.x); mx.y = fmaxf(mx.y, m.y);
            mx.z = fmaxf(mx.z, m.z); mx.w = fmaxf(mx.w, m.w);
            sm.x += q.x; sm.y += q.y; sm.z += q.z; sm.w += q.w;
            smax[ty][tx] = mx;
            ssum[ty][tx] = sm;
        }
        __syncthreads();
    }

    if (ty == 0) {
        const float inv = 1.0f / C;
        sm.x *= inv; sm.y *= inv; sm.z *= inv; sm.w *= inv;
        float4* pool4 = reinterpret_cast<float4*>(g_pooled);
        pool4[(b * 2 * HW) / 4 + hw4]      = mx;
        pool4[(b * 2 * HW + HW) / 4 + hw4] = sm;
    }
}

// ---------------------------------------------------------------------------
// Kernel 2: smem-tiled 7x7 conv + sigmoid, with the keyword bias computed
// redundantly per block (768 MACs over 256 threads, keyword/proj_w L2-hot).
// grid = (14, 32), 256 threads.
// ---------------------------------------------------------------------------
__global__ void conv_kernel(const float* __restrict__ conv_w,
                            const float* __restrict__ conv_b,
                            const float* __restrict__ keyword,
                            const float* __restrict__ proj_w,
                            const float* __restrict__ proj_b) {
    __shared__ float tile[2][CTH][CTW];   // 5 KB
    __shared__ float wts[98];
    __shared__ float wsum[8];
    __shared__ float sbias;

    int b  = blockIdx.y;
    int r0 = blockIdx.x * CROWS;
    int tid = threadIdx.x;

    if (tid < 98) wts[tid] = conv_w[tid];

    // --- keyword bias: dot(keyword[b], proj_w) + proj_b + conv_b ---
    {
        float s = 0.0f;
        const float* kb = keyword + b * KD;
#pragma unroll
        for (int k = tid; k < KD; k += 256)
            s += kb[k] * proj_w[k];
#pragma unroll
        for (int off = 16; off > 0; off >>= 1)
            s += __shfl_down_sync(0xFFFFFFFFu, s, off);
        if ((tid & 31) == 0) wsum[tid >> 5] = s;
    }

    // --- cooperative pooled-tile load (overlaps with reduction latency) ---
    const float* pb = g_pooled + b * 2 * HW;
    for (int i = tid; i < 2 * CTH * CTW; i += 256) {
        int ci = i / (CTH * CTW);
        int rr = (i / CTW) % CTH;
        int cc = i % CTW;
        int hh = r0 + rr - 3;
        int ww = cc - 3;
        float v = 0.0f;
        if ((unsigned)hh < (unsigned)H && (unsigned)ww < (unsigned)W)
            v = pb[ci * HW + hh * W + ww];
        tile[ci][rr][cc] = v;
    }
    __syncthreads();

    if (tid == 0) {
        float t = 0.0f;
#pragma unroll
        for (int i = 0; i < 8; ++i) t += wsum[i];
        sbias = t + proj_b[0] + conv_b[0];
    }
    __syncthreads();

    if (tid < CROWS * W) {
        int r = tid / W;
        int w = tid - r * W;
        float acc = sbias;
#pragma unroll
        for (int ci = 0; ci < 2; ++ci) {
#pragma unroll
            for (int kh = 0; kh < 7; ++kh) {
#pragma unroll
                for (int kw = 0; kw < 7; ++kw) {
                    acc += tile[ci][r + kh][w + kw] * wts[ci * 49 + kh * 7 + kw];
                }
            }
        }
        g_scale[b * HW + (r0 + r) * W + w] = 1.0f / (1.0f + __expf(-acc));
    }
}

// ---------------------------------------------------------------------------
// Kernel 3: out = x * scale (broadcast over C). float4 streaming.
// ---------------------------------------------------------------------------
__global__ void mul_kernel(const float4* __restrict__ x4,
                           float4* __restrict__ out4) {
    const int CHW4 = C * HW4;
    int i = blockIdx.x * blockDim.x + threadIdx.x;
    if (i >= (int)(NTOT / 4)) return;
    int b   = i / CHW4;
    int rem = i - b * CHW4;
    int hw4 = rem % HW4;

    float4 s = reinterpret_cast<const float4*>(g_scale)[b * HW4 + hw4];
    float4 v = __ldcs(x4 + i);
    v.x *= s.x; v.y *= s.y; v.z *= s.z; v.w *= s.w;
    __stcs(out4 + i, v);
}

// ---------------------------------------------------------------------------
extern "C" void kernel_launch(void* const* d_in, const int* in_sizes, int n_in,
                              void* d_out, int out_size) {
    const float* x       = (const float*)d_in[0];
    const float* keyword = (const float*)d_in[1];
    const float* conv_w  = (const float*)d_in[2];
    const float* conv_b  = (const float*)d_in[3];
    const float* proj_w  = (const float*)d_in[4];
    const float* proj_b  = (const float*)d_in[5];
    float* out = (float*)d_out;

    {
        dim3 grid(PBLK_PER_B, B);        // 49 x 32
        pool_kernel<<<grid, PTX * PTY>>>((const float4*)x);
    }
    {
        dim3 grid(H / CROWS, B);         // 14 x 32
        conv_kernel<<<grid, 256>>>(conv_w, conv_b, keyword, proj_w, proj_b);
    }
    {
        int n4 = (int)(NTOT / 4);
        mul_kernel<<<(n4 + 255) / 256, 256>>>((const float4*)x, (float4*)out);
    }
}

// round 7
// speedup vs baseline: 1.1186x; 1.0053x over previous
#include <cuda_runtime.h>
#include <cfloat>

#define B   32
#define C   512
#define H   56
#define W   56
#define HW  (H * W)          // 3136
#define HW4 (HW / 4)         // 784
#define KD  768
#define NTOT ((size_t)B * C * HW)

// pooling block geometry: 16 hw4-columns x 8 channel-chunks, 128 threads
#define PTX 16
#define PTY 8
#define PCC (C / PTY)        // 64 channels per thread
#define PBLK_PER_B (HW4 / PTX)   // 49

// conv tiling
#define CROWS 4
#define CTH   (CROWS + 6)
#define CTW   64

// Scratch (alloc-free rule: __device__ globals)
__device__ float g_pooled[B * 2 * HW];
__device__ float g_scale[B * HW];

// ---------------------------------------------------------------------------
// Kernel 1: fused channel max+mean pooling.
// 128-thread blocks -> up to 16 blocks/SM (full occupancy), 64-deep MLP per
// thread, 3-stage smem reduce.
// ---------------------------------------------------------------------------
__global__ void __launch_bounds__(PTX * PTY)
pool_kernel(const float4* __restrict__ x4) {
    int tx = threadIdx.x & (PTX - 1);
    int ty = threadIdx.x >> 4;            // 0..7
    int b   = blockIdx.y;
    int hw4 = blockIdx.x * PTX + tx;

    const float4* p = x4 + (size_t)b * C * HW4
                         + (size_t)ty * PCC * HW4 + hw4;
    float4 v0 = __ldg(p);
    float4 mx = v0;
    float4 sm = v0;
#pragma unroll 16
    for (int c = 1; c < PCC; ++c) {
        float4 v = __ldg(p + (size_t)c * HW4);
        mx.x = fmaxf(mx.x, v.x); mx.y = fmaxf(mx.y, v.y);
        mx.z = fmaxf(mx.z, v.z); mx.w = fmaxf(mx.w, v.w);
        sm.x += v.x; sm.y += v.y; sm.z += v.z; sm.w += v.w;
    }

    __shared__ float4 smax[PTY][PTX];
    __shared__ float4 ssum[PTY][PTX];
    smax[ty][tx] = mx;
    ssum[ty][tx] = sm;
    __syncthreads();

#pragma unroll
    for (int s = PTY / 2; s > 0; s >>= 1) {
        if (ty < s) {
            float4 m = smax[ty + s][tx];
            float4 q = ssum[ty + s][tx];
            mx.x = fmaxf(mx.x, m.x); mx.y = fmaxf(mx.y, m.y);
            mx.z = fmaxf(mx.z, m.z); mx.w = fmaxf(mx.w, m.w);
            sm.x += q.x; sm.y += q.y; sm.z += q.z; sm.w += q.w;
            smax[ty][tx] = mx;
            ssum[ty][tx] = sm;
        }
        __syncthreads();
    }

    if (ty == 0) {
        const float inv = 1.0f / C;
        sm.x *= inv; sm.y *= inv; sm.z *= inv; sm.w *= inv;
        float4* pool4 = reinterpret_cast<float4*>(g_pooled);
        pool4[(b * 2 * HW) / 4 + hw4]      = mx;
        pool4[(b * 2 * HW + HW) / 4 + hw4] = sm;
    }
}

// ---------------------------------------------------------------------------
// Kernel 2: smem-tiled 7x7 conv + sigmoid, keyword bias folded in (R6-proven).
// grid = (14, 32), 256 threads.
// ---------------------------------------------------------------------------
__global__ void conv_kernel(const float* __restrict__ conv_w,
                            const float* __restrict__ conv_b,
                            const float* __restrict__ keyword,
                            const float* __restrict__ proj_w,
                            const float* __restrict__ proj_b) {
    __shared__ float tile[2][CTH][CTW];   // 5 KB
    __shared__ float wts[98];
    __shared__ float wsum[8];
    __shared__ float sbias;

    int b  = blockIdx.y;
    int r0 = blockIdx.x * CROWS;
    int tid = threadIdx.x;

    if (tid < 98) wts[tid] = conv_w[tid];

    // keyword bias: dot(keyword[b], proj_w) + proj_b + conv_b
    {
        float s = 0.0f;
        const float* kb = keyword + b * KD;
#pragma unroll
        for (int k = tid; k < KD; k += 256)
            s += kb[k] * proj_w[k];
#pragma unroll
        for (int off = 16; off > 0; off >>= 1)
            s += __shfl_down_sync(0xFFFFFFFFu, s, off);
        if ((tid & 31) == 0) wsum[tid >> 5] = s;
    }

    // cooperative pooled-tile load
    const float* pb = g_pooled + b * 2 * HW;
    for (int i = tid; i < 2 * CTH * CTW; i += 256) {
        int ci = i / (CTH * CTW);
        int rr = (i / CTW) % CTH;
        int cc = i % CTW;
        int hh = r0 + rr - 3;
        int ww = cc - 3;
        float v = 0.0f;
        if ((unsigned)hh < (unsigned)H && (unsigned)ww < (unsigned)W)
            v = pb[ci * HW + hh * W + ww];
        tile[ci][rr][cc] = v;
    }
    __syncthreads();

    if (tid == 0) {
        float t = 0.0f;
#pragma unroll
        for (int i = 0; i < 8; ++i) t += wsum[i];
        sbias = t + proj_b[0] + conv_b[0];
    }
    __syncthreads();

    if (tid < CROWS * W) {
        int r = tid / W;
        int w = tid - r * W;
        float acc = sbias;
#pragma unroll
        for (int ci = 0; ci < 2; ++ci) {
#pragma unroll
            for (int kh = 0; kh < 7; ++kh) {
#pragma unroll
                for (int kw = 0; kw < 7; ++kw) {
                    acc += tile[ci][r + kh][w + kw] * wts[ci * 49 + kh * 7 + kw];
                }
            }
        }
        g_scale[b * HW + (r0 + r) * W + w] = 1.0f / (1.0f + __expf(-acc));
    }
}

// ---------------------------------------------------------------------------
// Kernel 3: out = x * scale (broadcast over C). float4 streaming.
// ---------------------------------------------------------------------------
__global__ void mul_kernel(const float4* __restrict__ x4,
                           float4* __restrict__ out4) {
    const int CHW4 = C * HW4;
    int i = blockIdx.x * blockDim.x + threadIdx.x;
    if (i >= (int)(NTOT / 4)) return;
    int b   = i / CHW4;
    int rem = i - b * CHW4;
    int hw4 = rem % HW4;

    float4 s = reinterpret_cast<const float4*>(g_scale)[b * HW4 + hw4];
    float4 v = __ldcs(x4 + i);
    v.x *= s.x; v.y *= s.y; v.z *= s.z; v.w *= s.w;
    __stcs(out4 + i, v);
}

// ---------------------------------------------------------------------------
extern "C" void kernel_launch(void* const* d_in, const int* in_sizes, int n_in,
                              void* d_out, int out_size) {
    const float* x       = (const float*)d_in[0];
    const float* keyword = (const float*)d_in[1];
    const float* conv_w  = (const float*)d_in[2];
    const float* conv_b  = (const float*)d_in[3];
    const float* proj_w  = (const float*)d_in[4];
    const float* proj_b  = (const float*)d_in[5];
    float* out = (float*)d_out;

    {
        dim3 grid(PBLK_PER_B, B);        // 49 x 32
        pool_kernel<<<grid, PTX * PTY>>>((const float4*)x);
    }
    {
        dim3 grid(H / CROWS, B);         // 14 x 32
        conv_kernel<<<grid, 256>>>(conv_w, conv_b, keyword, proj_w, proj_b);
    }
    {
        int n4 = (int)(NTOT / 4);
        mul_kernel<<<(n4 + 255) / 256, 256>>>((const float4*)x, (float4*)out);
    }
}